// round 9
// baseline (speedup 1.0000x reference)
#include <cuda_runtime.h>
#include <cuda_fp16.h>
#include <cstdint>

#define Ss 2048
#define Dd 64
constexpr int BH  = 32;
constexpr int QT  = 64;            // q rows per CTA
constexpr int KT  = 128;           // k cols per tile
constexpr int NTH = 256;           // 8 warps: 4 row-groups x 2 col-halves
constexpr int NT  = Ss / KT;       // 16
constexpr long long OUT_ELEMS = (long long)BH * Ss * Dd;
constexpr long long ATT_ELEMS = (long long)BH * Ss * (long long)Ss;

// static device scratch
__device__ __align__(256) __half g_qh[(size_t)BH * Ss * Dd];   // pre-scaled by log2e/8
__device__ __align__(256) __half g_kh[(size_t)BH * Ss * Dd];
__device__ __align__(256) __half g_vh[(size_t)BH * Ss * Dd];
__device__ __align__(256) unsigned char g_m8[(size_t)2 * Ss * Ss];
__device__ __align__(256) __half g_uh[(size_t)ATT_ELEMS];      // unnormalized exp(e), fp16

// smem layout (bytes)
constexpr int OFF_RED = 0;                        // srows[2][64] + srinv[64]
constexpr int OFF_Q   = 1024;                     // P1: 64 x 144 = 9216
constexpr int KSTG    = 128 * 144;                // 18432
constexpr int OFF_K   = 10240;                    // P1: 3 stages -> 65536
constexpr int MSTG    = 64 * 144;                 // 9216
constexpr int OFF_M   = 65536;                    // P1: 3 stages -> 93184
constexpr int USTG    = 64 * 272;                 // 17408
constexpr int OFF_U   = 1024;                     // P2 overlay: 3 stages -> 53248
constexpr int OFF_V   = 53248;                    // P2: 3 stages -> 108544
constexpr int SMEM_BYTES = 108544;                // 2 CTAs/SM (<= 113 KB)

__device__ __forceinline__ uint32_t smem_u32(const void* p) {
    uint32_t a;
    asm("{ .reg .u64 t; cvta.to.shared.u64 t, %1; cvt.u32.u64 %0, t; }" : "=r"(a) : "l"(p));
    return a;
}
__device__ __forceinline__ void ldsm4(uint32_t r[4], uint32_t a) {
    asm volatile("ldmatrix.sync.aligned.m8n8.x4.shared.b16 {%0,%1,%2,%3}, [%4];"
                 : "=r"(r[0]), "=r"(r[1]), "=r"(r[2]), "=r"(r[3]) : "r"(a) : "memory");
}
__device__ __forceinline__ void ldsm4t(uint32_t r[4], uint32_t a) {
    asm volatile("ldmatrix.sync.aligned.m8n8.x4.trans.shared.b16 {%0,%1,%2,%3}, [%4];"
                 : "=r"(r[0]), "=r"(r[1]), "=r"(r[2]), "=r"(r[3]) : "r"(a) : "memory");
}
__device__ __forceinline__ void mma16816(float c[4], const uint32_t a[4], uint32_t b0, uint32_t b1) {
    asm volatile(
        "mma.sync.aligned.m16n8k16.row.col.f32.f16.f16.f32 "
        "{%0,%1,%2,%3}, {%4,%5,%6,%7}, {%8,%9}, {%0,%1,%2,%3};"
        : "+f"(c[0]), "+f"(c[1]), "+f"(c[2]), "+f"(c[3])
        : "r"(a[0]), "r"(a[1]), "r"(a[2]), "r"(a[3]), "r"(b0), "r"(b1));
}
__device__ __forceinline__ uint32_t packh2(float x, float y) {
    __half2 h = __floats2half2_rn(x, y);
    return *(uint32_t*)&h;
}
__device__ __forceinline__ float ex2f(float x) {
    float r; asm("ex2.approx.f32 %0, %1;" : "=f"(r) : "f"(x)); return r;
}
__device__ __forceinline__ uint32_t lds_u16(uint32_t a) {
    uint32_t v; asm volatile("ld.shared.u16 %0, [%1];" : "=r"(v) : "r"(a)); return v;
}
#define CPA16(dst, src) asm volatile("cp.async.cg.shared.global [%0], [%1], 16;" :: "r"(dst), "l"(src))
#define CP_COMMIT()     asm volatile("cp.async.commit_group;" ::: "memory")
#define CP_WAIT0()      asm volatile("cp.async.wait_group 0;" ::: "memory")
#define CP_WAIT1()      asm volatile("cp.async.wait_group 1;" ::: "memory")
#define CP_WAIT2()      asm volatile("cp.async.wait_group 2;" ::: "memory")
#define BARH()          asm volatile("bar.sync %0, 128;" :: "r"(h + 1) : "memory")

constexpr int QKV_BLOCKS  = 3 * (BH * Ss * Dd / 4) / 256;       // 12288
constexpr int MASK_BLOCKS = (2 * Ss * Ss / 4) / 256;            // 8192
constexpr float QSCALE = 0.18033688011112042f;                  // log2(e)/8

__global__ void __launch_bounds__(256) cvt_all(const float* __restrict__ Q,
                                               const float* __restrict__ K,
                                               const float* __restrict__ V,
                                               const int* __restrict__ M)
{
    if (blockIdx.x < QKV_BLOCKS) {
        const int n4 = BH * Ss * Dd / 4;
        int id = blockIdx.x * 256 + threadIdx.x;
        const float* src; __half* dst; float s;
        int i = id;
        if (id < n4)          { src = Q; dst = g_qh; s = QSCALE; }
        else if (id < 2 * n4) { src = K; dst = g_kh; s = 1.f; i -= n4; }
        else                  { src = V; dst = g_vh; s = 1.f; i -= 2 * n4; }
        float4 v = ((const float4*)src)[i];
        uint2 u; u.x = packh2(v.x * s, v.y * s); u.y = packh2(v.z * s, v.w * s);
        ((uint2*)dst)[i] = u;
    } else {
        int i = (blockIdx.x - QKV_BLOCKS) * 256 + threadIdx.x;
        int4 m = ((const int4*)M)[i];
        uchar4 o; o.x = (unsigned char)m.x; o.y = (unsigned char)m.y;
        o.z = (unsigned char)m.z; o.w = (unsigned char)m.w;
        ((uchar4*)g_m8)[i] = o;
    }
}

extern __shared__ __align__(16) char sm[];

// ---------- pass 1 tile body: wait-at-top, prefetch distance 2 ----------
#define P1_BODY(T, CUR, PF) do {                                           \
    if ((T) + 1 < NT) CP_WAIT1(); else CP_WAIT0();                         \
    BARH();                                                                \
    if ((T) + 2 < NT) {                                                    \
        CPA16(kdst0 + (PF) * KSTG,        kpre);                           \
        CPA16(kdst0 + (PF) * KSTG + 2304, kpre + 1024);                    \
        CPA16(kdst0 + (PF) * KSTG + 4608, kpre + 2048);                    \
        CPA16(kdst0 + (PF) * KSTG + 6912, kpre + 3072);                    \
        CPA16(mdst0 + (PF) * MSTG,        mpre);                           \
        CPA16(mdst0 + (PF) * MSTG + 4608, mpre + (size_t)32 * Ss);         \
        CP_COMMIT();                                                       \
        kpre += 8192; mpre += KT;                                          \
    }                                                                      \
    float c[8][4];                                                         \
    _Pragma("unroll") for (int nt = 0; nt < 8; nt++) {                     \
        c[nt][0] = 0.f; c[nt][1] = 0.f; c[nt][2] = 0.f; c[nt][3] = 0.f; }  \
    _Pragma("unroll") for (int kc = 0; kc < 4; kc++)                       \
        _Pragma("unroll") for (int np = 0; np < 4; np++) {                 \
            uint32_t bf[4];                                                \
            ldsm4(bf, kfr + (CUR) * KSTG + np * 2304 + kc * 32);           \
            mma16816(c[2 * np],     aQ[kc], bf[0], bf[1]);                 \
            mma16816(c[2 * np + 1], aQ[kc], bf[2], bf[3]);                 \
        }                                                                  \
    _Pragma("unroll") for (int nt = 0; nt < 8; nt++) {                     \
        uint32_t m0 = lds_u16(mep + (CUR) * MSTG + 8 * nt);                \
        uint32_t m1 = lds_u16(mep + (CUR) * MSTG + 1152 + 8 * nt);         \
        float u0 = (m0 & 0xFF) ? ex2f(c[nt][0]) : 0.f;                     \
        float u1 = (m0 >> 8)   ? ex2f(c[nt][1]) : 0.f;                     \
        float u2 = (m1 & 0xFF) ? ex2f(c[nt][2]) : 0.f;                     \
        float u3 = (m1 >> 8)   ? ex2f(c[nt][3]) : 0.f;                     \
        rs0 += u0 + u1; rs1 += u2 + u3;                                    \
        *(uint32_t*)(ug + 8 * nt)          = packh2(u0, u1);               \
        *(uint32_t*)(ug + 8 * Ss + 8 * nt) = packh2(u2, u3);               \
    }                                                                      \
    ug += KT;                                                              \
} while (0)

// ---------- pass 2 tile body ----------
#define P2_BODY(T, CUR, PF) do {                                           \
    if ((T) + 1 < NT) CP_WAIT1(); else CP_WAIT0();                         \
    BARH();                                                                \
    if ((T) + 2 < NT) {                                                    \
        CPA16(udst0 + (PF) * USTG,         upre);                          \
        CPA16(udst0 + (PF) * USTG +  4352, upre + (size_t)16 * Ss);        \
        CPA16(udst0 + (PF) * USTG +  8704, upre + (size_t)32 * Ss);        \
        CPA16(udst0 + (PF) * USTG + 13056, upre + (size_t)48 * Ss);        \
        CPA16(vdst0 + (PF) * KSTG,        vpre);                           \
        CPA16(vdst0 + (PF) * KSTG + 2304, vpre + 1024);                    \
        CPA16(vdst0 + (PF) * KSTG + 4608, vpre + 2048);                    \
        CPA16(vdst0 + (PF) * KSTG + 6912, vpre + 3072);                    \
        CP_COMMIT();                                                       \
        upre += KT; vpre += 8192;                                          \
    }                                                                      \
    _Pragma("unroll") for (int kc = 0; kc < 4; kc++) {                     \
        uint32_t a[4];                                                     \
        ldsm4(a, ufr + (CUR) * USTG + kc * 32);                            \
        _Pragma("unroll") for (int np = 0; np < 4; np++) {                 \
            uint32_t bf[4];                                                \
            ldsm4t(bf, vfr + (CUR) * KSTG + kc * 2304 + np * 32);          \
            mma16816(o[2 * np],     a, bf[0], bf[1]);                      \
            mma16816(o[2 * np + 1], a, bf[2], bf[3]);                      \
        }                                                                  \
        if (ar) {                                                          \
            float2 f0 = __half22float2(*(__half2*)&a[0]);                  \
            float2 f1 = __half22float2(*(__half2*)&a[1]);                  \
            float2 f2 = __half22float2(*(__half2*)&a[2]);                  \
            float2 f3 = __half22float2(*(__half2*)&a[3]);                  \
            *(float2*)(ar + 16 * kc)              = make_float2(f0.x * rv0, f0.y * rv0); \
            *(float2*)(ar + 8 * Ss + 16 * kc)     = make_float2(f1.x * rv1, f1.y * rv1); \
            *(float2*)(ar + 16 * kc + 8)          = make_float2(f2.x * rv0, f2.y * rv0); \
            *(float2*)(ar + 8 * Ss + 16 * kc + 8) = make_float2(f3.x * rv1, f3.y * rv1); \
        }                                                                  \
    }                                                                      \
    if (ar) ar += KT;                                                      \
} while (0)

__global__ void __launch_bounds__(NTH, 2)
attn_kernel(float* __restrict__ out, float* __restrict__ att)
{
    const int tid  = threadIdx.x;
    const int lane = tid & 31;
    const int warp = tid >> 5;
    const int g    = lane >> 2;
    const int tg   = lane & 3;
    const int lm   = lane >> 3;
    const int ll   = lane & 7;
    const int rgrp = warp & 3;         // q-row group (16 rows)
    const int h    = warp >> 2;        // k-col half (64 cols) == tid>>7

    const int q0 = blockIdx.x * QT;
    const int bh = blockIdx.y;
    const int b  = bh >> 4;

    const uint32_t smb = smem_u32(sm);
    float* srows = (float*)(sm + OFF_RED);          // [2][64]
    float* srinv = (float*)(sm + OFF_RED + 512);    // [64]

    const __half* qsrc = g_qh + ((size_t)bh * Ss + q0) * Dd;
    const __half* ksrc = g_kh + (size_t)bh * Ss * Dd;
    const __half* vsrc = g_vh + (size_t)bh * Ss * Dd;
    const unsigned char* msrc = g_m8 + (size_t)b * Ss * Ss + (size_t)q0 * Ss;
    __half* usrc = g_uh + ((size_t)bh * Ss + q0) * Ss;
    float* attg = att ? (att + (size_t)bh * Ss * (size_t)Ss) : nullptr;

    const int r0 = rgrp * 16 + g;
    const int r1 = r0 + 8;

    // ---- per-half cp.async base addresses (each half loads only its slice) ----
    const int lt = tid & 127;          // thread-in-half
    const int hb = h * 64;             // k-row / k-col base for this half
    const uint32_t kdst0 = smb + OFF_K + (uint32_t)((hb + (lt >> 3)) * 144 + (lt & 7) * 16);
    const uint32_t vdst0 = smb + OFF_V + (uint32_t)((hb + (lt >> 3)) * 144 + (lt & 7) * 16);
    const uint32_t mdst0 = smb + OFF_M + (uint32_t)((lt >> 2) * 144 + hb + (lt & 3) * 16);
    const uint32_t udst0 = smb + OFF_U + (uint32_t)((lt >> 3) * 272 + h * 128 + (lt & 7) * 16);
    const __half* ksrcT = ksrc + (hb + (lt >> 3)) * 64 + (lt & 7) * 8;
    const __half* vsrcT = vsrc + (hb + (lt >> 3)) * 64 + (lt & 7) * 8;
    const unsigned char* msrcT = msrc + (size_t)(lt >> 2) * Ss + hb + (lt & 3) * 16;
    const __half* usrcT = usrc + (size_t)(lt >> 3) * Ss + hb + (lt & 7) * 8;

    // ---- fragment bases ----
    const uint32_t qfr = smb + OFF_Q + (uint32_t)((rgrp * 16 + (lm & 1) * 8 + ll) * 144 + (lm >> 1) * 16);
    const uint32_t kfr = smb + OFF_K + (uint32_t)((hb + (lm >> 1) * 8 + ll) * 144 + (lm & 1) * 16);
    const uint32_t vfr = smb + OFF_V + (uint32_t)((hb + (lm & 1) * 8 + ll) * 144 + (lm >> 1) * 16);
    const uint32_t ufr = smb + OFF_U + (uint32_t)((rgrp * 16 + (lm & 1) * 8 + ll) * 272 + h * 128 + (lm >> 1) * 16);
    const uint32_t mep = smb + OFF_M + (uint32_t)(r0 * 144 + hb + 2 * tg);

    // ---- pass-1 prologue: Q (group 0), tile0 -> stage0 (G1), tile1 -> stage1 (G2) ----
    CPA16(smb + OFF_Q + (tid >> 3) * 144 + (tid & 7) * 16, qsrc + (tid >> 3) * 64 + (tid & 7) * 8);
    CPA16(smb + OFF_Q + ((tid >> 3) + 32) * 144 + (tid & 7) * 16, qsrc + ((tid >> 3) + 32) * 64 + (tid & 7) * 8);
    CP_COMMIT();
    {
        const __half* kp = ksrcT;
        const unsigned char* mp = msrcT;
        CPA16(kdst0,        kp);
        CPA16(kdst0 + 2304, kp + 1024);
        CPA16(kdst0 + 4608, kp + 2048);
        CPA16(kdst0 + 6912, kp + 3072);
        CPA16(mdst0,        mp);
        CPA16(mdst0 + 4608, mp + (size_t)32 * Ss);
        CP_COMMIT();
        CPA16(kdst0 + KSTG,        kp + 8192);
        CPA16(kdst0 + KSTG + 2304, kp + 8192 + 1024);
        CPA16(kdst0 + KSTG + 4608, kp + 8192 + 2048);
        CPA16(kdst0 + KSTG + 6912, kp + 8192 + 3072);
        CPA16(mdst0 + MSTG,        mp + KT);
        CPA16(mdst0 + MSTG + 4608, mp + KT + (size_t)32 * Ss);
        CP_COMMIT();
    }
    CP_WAIT2();               // Q group retired
    __syncthreads();
    uint32_t aQ[4][4];
    #pragma unroll
    for (int kc = 0; kc < 4; kc++) ldsm4(aQ[kc], qfr + kc * 32);

    // ================= PASS 1: row sums + u-fp16 store =================
    float rs0 = 0.f, rs1 = 0.f;
    {
        const __half* kpre = ksrcT + 2 * 8192;
        const unsigned char* mpre = msrcT + 2 * KT;
        __half* ug = usrc + (size_t)r0 * Ss + hb + 2 * tg;
        #pragma unroll 1
        for (int t3 = 0; t3 < 15; t3 += 3) {
            P1_BODY(t3,     0, 2);
            P1_BODY(t3 + 1, 1, 0);
            P1_BODY(t3 + 2, 2, 1);
        }
        P1_BODY(15, 0, 0);
    }

    // reduce quad lanes, then the 2 col-halves; reciprocals
    rs0 += __shfl_xor_sync(0xffffffffu, rs0, 1); rs0 += __shfl_xor_sync(0xffffffffu, rs0, 2);
    rs1 += __shfl_xor_sync(0xffffffffu, rs1, 1); rs1 += __shfl_xor_sync(0xffffffffu, rs1, 2);
    __syncthreads();
    if (tg == 0) { srows[h * 64 + r0] = rs0; srows[h * 64 + r1] = rs1; }
    __syncthreads();
    if (tid < 64) {
        float s = srows[tid] + srows[64 + tid];
        srinv[tid] = (s > 0.f) ? (1.0f / s) : 0.f;
    }
    __syncthreads();
    const float rv0 = srinv[r0];
    const float rv1 = srinv[r1];

    // ================= PASS 2: PV + scaled att writeout =================
    float o[8][4];
    #pragma unroll
    for (int j = 0; j < 8; j++) { o[j][0] = 0.f; o[j][1] = 0.f; o[j][2] = 0.f; o[j][3] = 0.f; }

    // prologue: tile0 -> stage0, tile1 -> stage1
    {
        const __half* up = usrcT;
        const __half* vp = vsrcT;
        CPA16(udst0,         up);
        CPA16(udst0 +  4352, up + (size_t)16 * Ss);
        CPA16(udst0 +  8704, up + (size_t)32 * Ss);
        CPA16(udst0 + 13056, up + (size_t)48 * Ss);
        CPA16(vdst0,        vp);
        CPA16(vdst0 + 2304, vp + 1024);
        CPA16(vdst0 + 4608, vp + 2048);
        CPA16(vdst0 + 6912, vp + 3072);
        CP_COMMIT();
        CPA16(udst0 + USTG,         up + KT);
        CPA16(udst0 + USTG +  4352, up + KT + (size_t)16 * Ss);
        CPA16(udst0 + USTG +  8704, up + KT + (size_t)32 * Ss);
        CPA16(udst0 + USTG + 13056, up + KT + (size_t)48 * Ss);
        CPA16(vdst0 + KSTG,        vp + 8192);
        CPA16(vdst0 + KSTG + 2304, vp + 8192 + 1024);
        CPA16(vdst0 + KSTG + 4608, vp + 8192 + 2048);
        CPA16(vdst0 + KSTG + 6912, vp + 8192 + 3072);
        CP_COMMIT();
    }

    {
        const __half* upre = usrcT + 2 * KT;
        const __half* vpre = vsrcT + 2 * 8192;
        float* ar = attg ? (attg + (size_t)(q0 + r0) * Ss + hb + 2 * tg) : nullptr;
        #pragma unroll 1
        for (int t3 = 0; t3 < 15; t3 += 3) {
            P2_BODY(t3,     0, 2);
            P2_BODY(t3 + 1, 1, 0);
            P2_BODY(t3 + 2, 2, 1);
        }
        P2_BODY(15, 0, 0);
    }

    // ---- combine the two k-halves of O via smem, scale by rinv, write ----
    __syncthreads();
    float* ost = (float*)(sm + OFF_U);            // [64][66]
    if (h == 1) {
        #pragma unroll
        for (int j = 0; j < 8; j++) {
            *(float2*)&ost[r0 * 66 + 8 * j + 2 * tg] = make_float2(o[j][0], o[j][1]);
            *(float2*)&ost[r1 * 66 + 8 * j + 2 * tg] = make_float2(o[j][2], o[j][3]);
        }
    }
    __syncthreads();
    if (out && h == 0) {
        float* og0 = out + ((size_t)bh * Ss + q0 + r0) * Dd;
        float* og1 = out + ((size_t)bh * Ss + q0 + r1) * Dd;
        #pragma unroll
        for (int j = 0; j < 8; j++) {
            float2 s0 = *(float2*)&ost[r0 * 66 + 8 * j + 2 * tg];
            float2 s1 = *(float2*)&ost[r1 * 66 + 8 * j + 2 * tg];
            *(float2*)(og0 + 8 * j + 2 * tg) = make_float2((o[j][0] + s0.x) * rv0, (o[j][1] + s0.y) * rv0);
            *(float2*)(og1 + 8 * j + 2 * tg) = make_float2((o[j][2] + s1.x) * rv1, (o[j][3] + s1.y) * rv1);
        }
    }
}

extern "C" void kernel_launch(void* const* d_in, const int* in_sizes, int n_in,
                              void* d_out, int out_size)
{
    (void)in_sizes; (void)n_in;
    const float* Q = (const float*)d_in[0];
    const float* K = (const float*)d_in[1];
    const float* V = (const float*)d_in[2];
    const int*   M = (const int*)d_in[3];

    float* outp = nullptr;
    float* attp = nullptr;
    long long os = (long long)out_size;
    if (os >= OUT_ELEMS + ATT_ELEMS) {
        outp = (float*)d_out;
        attp = (float*)d_out + OUT_ELEMS;
    } else if (os >= ATT_ELEMS) {
        attp = (float*)d_out;
    } else {
        outp = (float*)d_out;
    }

    cvt_all<<<QKV_BLOCKS + MASK_BLOCKS, 256>>>(Q, K, V, M);

    cudaFuncSetAttribute(attn_kernel, cudaFuncAttributeMaxDynamicSharedMemorySize, SMEM_BYTES);
    dim3 grid(Ss / QT, BH);
    attn_kernel<<<grid, NTH, SMEM_BYTES>>>(outp, attp);
}

// round 10
// speedup vs baseline: 1.0202x; 1.0202x over previous
#include <cuda_runtime.h>
#include <cuda_fp16.h>
#include <cstdint>

#define Ss 2048
#define Dd 64
constexpr int BH  = 32;
constexpr int QT  = 64;            // q rows per CTA
constexpr int KT  = 128;           // k cols per tile
constexpr int NTH = 256;           // 8 warps: 4 row-groups x 2 col-halves
constexpr int NT  = Ss / KT;       // 16
constexpr long long OUT_ELEMS = (long long)BH * Ss * Dd;
constexpr long long ATT_ELEMS = (long long)BH * Ss * (long long)Ss;

// static device scratch
__device__ __align__(256) __half g_qh[(size_t)BH * Ss * Dd];   // pre-scaled by log2e/8
__device__ __align__(256) __half g_kh[(size_t)BH * Ss * Dd];
__device__ __align__(256) __half g_vh[(size_t)BH * Ss * Dd];
__device__ __align__(256) unsigned char g_m8[(size_t)2 * Ss * Ss];
__device__ __align__(256) __half g_uh[(size_t)ATT_ELEMS];      // unnormalized exp(e), fp16

// smem layout (bytes) — total 72,704 -> 3 CTAs/SM
constexpr int OFF_RED = 0;                        // srows[2][64] + srinv[64]
constexpr int OFF_Q   = 1024;                     // 64 x 144 = 9216
constexpr int KSTG    = 128 * 144;                // 18432
constexpr int OFF_K   = 10240;                    // P1: 2 stages -> 47104
constexpr int MSTG    = 64 * 144;                 // 9216
constexpr int OFF_M   = 47104;                    // P1: 2 stages -> 65536
constexpr int USTG    = 64 * 272;                 // 17408
constexpr int OFF_U   = 1024;                     // P2 overlay: 2 stages -> 35840
constexpr int OFF_V   = 35840;                    // P2: 2 stages -> 72704
constexpr int SMEM_BYTES = 72704;

__device__ __forceinline__ uint32_t smem_u32(const void* p) {
    uint32_t a;
    asm("{ .reg .u64 t; cvta.to.shared.u64 t, %1; cvt.u32.u64 %0, t; }" : "=r"(a) : "l"(p));
    return a;
}
__device__ __forceinline__ void ldsm4(uint32_t r[4], uint32_t a) {
    asm volatile("ldmatrix.sync.aligned.m8n8.x4.shared.b16 {%0,%1,%2,%3}, [%4];"
                 : "=r"(r[0]), "=r"(r[1]), "=r"(r[2]), "=r"(r[3]) : "r"(a) : "memory");
}
__device__ __forceinline__ void ldsm4t(uint32_t r[4], uint32_t a) {
    asm volatile("ldmatrix.sync.aligned.m8n8.x4.trans.shared.b16 {%0,%1,%2,%3}, [%4];"
                 : "=r"(r[0]), "=r"(r[1]), "=r"(r[2]), "=r"(r[3]) : "r"(a) : "memory");
}
__device__ __forceinline__ void mma16816(float c[4], const uint32_t a[4], uint32_t b0, uint32_t b1) {
    asm volatile(
        "mma.sync.aligned.m16n8k16.row.col.f32.f16.f16.f32 "
        "{%0,%1,%2,%3}, {%4,%5,%6,%7}, {%8,%9}, {%0,%1,%2,%3};"
        : "+f"(c[0]), "+f"(c[1]), "+f"(c[2]), "+f"(c[3])
        : "r"(a[0]), "r"(a[1]), "r"(a[2]), "r"(a[3]), "r"(b0), "r"(b1));
}
__device__ __forceinline__ uint32_t packh2(float x, float y) {
    __half2 h = __floats2half2_rn(x, y);
    return *(uint32_t*)&h;
}
__device__ __forceinline__ float ex2f(float x) {
    float r; asm("ex2.approx.f32 %0, %1;" : "=f"(r) : "f"(x)); return r;
}
__device__ __forceinline__ uint32_t lds_u16(uint32_t a) {
    uint32_t v; asm volatile("ld.shared.u16 %0, [%1];" : "=r"(v) : "r"(a)); return v;
}
#define CPA16(dst, src) asm volatile("cp.async.cg.shared.global [%0], [%1], 16;" :: "r"(dst), "l"(src))
#define CP_COMMIT()     asm volatile("cp.async.commit_group;" ::: "memory")
#define CP_WAIT0()      asm volatile("cp.async.wait_group 0;" ::: "memory")

constexpr int QKV_BLOCKS  = 3 * (BH * Ss * Dd / 4) / 256;       // 12288
constexpr int MASK_BLOCKS = (2 * Ss * Ss / 4) / 256;            // 8192
constexpr float QSCALE = 0.18033688011112042f;                  // log2(e)/8

__global__ void __launch_bounds__(256) cvt_all(const float* __restrict__ Q,
                                               const float* __restrict__ K,
                                               const float* __restrict__ V,
                                               const int* __restrict__ M)
{
    if (blockIdx.x < QKV_BLOCKS) {
        const int n4 = BH * Ss * Dd / 4;
        int id = blockIdx.x * 256 + threadIdx.x;
        const float* src; __half* dst; float s;
        int i = id;
        if (id < n4)          { src = Q; dst = g_qh; s = QSCALE; }
        else if (id < 2 * n4) { src = K; dst = g_kh; s = 1.f; i -= n4; }
        else                  { src = V; dst = g_vh; s = 1.f; i -= 2 * n4; }
        float4 v = ((const float4*)src)[i];
        uint2 u; u.x = packh2(v.x * s, v.y * s); u.y = packh2(v.z * s, v.w * s);
        ((uint2*)dst)[i] = u;
    } else {
        int i = (blockIdx.x - QKV_BLOCKS) * 256 + threadIdx.x;
        int4 m = ((const int4*)M)[i];
        uchar4 o; o.x = (unsigned char)m.x; o.y = (unsigned char)m.y;
        o.z = (unsigned char)m.z; o.w = (unsigned char)m.w;
        ((uchar4*)g_m8)[i] = o;
    }
}

extern __shared__ __align__(16) char sm[];

// ---------------- pass 1 tile body (epilogue chunked: c4[4][4]) ----------------
#define P1_BODY(T, CUR, NXT) do {                                          \
    if ((T) + 1 < NT) {                                                    \
        CPA16(kdst##NXT,         kpre);                                    \
        CPA16(kdst##NXT +  4608, kpre + 2048);                             \
        CPA16(kdst##NXT +  9216, kpre + 4096);                             \
        CPA16(kdst##NXT + 13824, kpre + 6144);                             \
        CPA16(mdst##NXT,         mpre);                                    \
        CPA16(mdst##NXT + 4608,  mpre + (size_t)32 * Ss);                  \
        CP_COMMIT();                                                       \
        kpre += (size_t)KT * Dd; mpre += KT;                               \
    }                                                                      \
    _Pragma("unroll") for (int ch = 0; ch < 2; ch++) {                     \
        float c4[4][4];                                                    \
        _Pragma("unroll") for (int j = 0; j < 4; j++) {                    \
            c4[j][0] = 0.f; c4[j][1] = 0.f; c4[j][2] = 0.f; c4[j][3] = 0.f; } \
        _Pragma("unroll") for (int kc = 0; kc < 4; kc++)                   \
            _Pragma("unroll") for (int j = 0; j < 2; j++) {                \
                uint32_t bf[4];                                            \
                ldsm4(bf, kfr##CUR + (2 * ch + j) * 2304 + kc * 32);       \
                mma16816(c4[2 * j],     aQ[kc], bf[0], bf[1]);             \
                mma16816(c4[2 * j + 1], aQ[kc], bf[2], bf[3]);             \
            }                                                              \
        _Pragma("unroll") for (int j = 0; j < 4; j++) {                    \
            const int nt = 4 * ch + j;                                     \
            uint32_t m0 = lds_u16(mep##CUR + 8 * nt);                      \
            uint32_t m1 = lds_u16(mep##CUR + 1152 + 8 * nt);               \
            float u0 = (m0 & 0xFF) ? ex2f(c4[j][0]) : 0.f;                 \
            float u1 = (m0 >> 8)   ? ex2f(c4[j][1]) : 0.f;                 \
            float u2 = (m1 & 0xFF) ? ex2f(c4[j][2]) : 0.f;                 \
            float u3 = (m1 >> 8)   ? ex2f(c4[j][3]) : 0.f;                 \
            rs0 += u0 + u1; rs1 += u2 + u3;                                \
            *(uint32_t*)(ug + 8 * nt)          = packh2(u0, u1);           \
            *(uint32_t*)(ug + 8 * Ss + 8 * nt) = packh2(u2, u3);           \
        }                                                                  \
    }                                                                      \
    ug += KT;                                                              \
    if ((T) + 1 < NT) { CP_WAIT0(); __syncthreads(); }                     \
} while (0)

// ---------------- pass 2 tile body ----------------
#define P2_BODY(T, CUR, NXT) do {                                          \
    if ((T) + 1 < NT) {                                                    \
        CPA16(udst##NXT,         upre);                                    \
        CPA16(udst##NXT +  4352, upre + (size_t)16 * Ss);                  \
        CPA16(udst##NXT +  8704, upre + (size_t)32 * Ss);                  \
        CPA16(udst##NXT + 13056, upre + (size_t)48 * Ss);                  \
        CPA16(vdst##NXT,         vpre);                                    \
        CPA16(vdst##NXT +  4608, vpre + 2048);                             \
        CPA16(vdst##NXT +  9216, vpre + 4096);                             \
        CPA16(vdst##NXT + 13824, vpre + 6144);                             \
        CP_COMMIT();                                                       \
        upre += KT; vpre += (size_t)KT * Dd;                               \
    }                                                                      \
    _Pragma("unroll") for (int kc = 0; kc < 4; kc++) {                     \
        uint32_t a[4];                                                     \
        ldsm4(a, ufr##CUR + kc * 32);                                      \
        _Pragma("unroll") for (int np = 0; np < 4; np++) {                 \
            uint32_t bf[4];                                                \
            ldsm4t(bf, vfr##CUR + kc * 2304 + np * 32);                    \
            mma16816(o[2 * np],     a, bf[0], bf[1]);                      \
            mma16816(o[2 * np + 1], a, bf[2], bf[3]);                      \
        }                                                                  \
        if (ar) {                                                          \
            float2 f0 = __half22float2(*(__half2*)&a[0]);                  \
            float2 f1 = __half22float2(*(__half2*)&a[1]);                  \
            float2 f2 = __half22float2(*(__half2*)&a[2]);                  \
            float2 f3 = __half22float2(*(__half2*)&a[3]);                  \
            *(float2*)(ar + 16 * kc)              = make_float2(f0.x * rv0, f0.y * rv0); \
            *(float2*)(ar + 8 * Ss + 16 * kc)     = make_float2(f1.x * rv1, f1.y * rv1); \
            *(float2*)(ar + 16 * kc + 8)          = make_float2(f2.x * rv0, f2.y * rv0); \
            *(float2*)(ar + 8 * Ss + 16 * kc + 8) = make_float2(f3.x * rv1, f3.y * rv1); \
        }                                                                  \
    }                                                                      \
    if (ar) ar += KT;                                                      \
    if ((T) + 1 < NT) { CP_WAIT0(); __syncthreads(); }                     \
} while (0)

__global__ void __launch_bounds__(NTH, 3)
attn_kernel(float* __restrict__ out, float* __restrict__ att)
{
    const int tid  = threadIdx.x;
    const int lane = tid & 31;
    const int warp = tid >> 5;
    const int g    = lane >> 2;
    const int tg   = lane & 3;
    const int lm   = lane >> 3;
    const int ll   = lane & 7;
    const int rgrp = warp & 3;         // q-row group (16 rows)
    const int h    = warp >> 2;        // k-col half (64 cols)

    const int q0 = blockIdx.x * QT;
    const int bh = blockIdx.y;
    const int b  = bh >> 4;

    const uint32_t smb = smem_u32(sm);
    float* srows = (float*)(sm + OFF_RED);          // [2][64]
    float* srinv = (float*)(sm + OFF_RED + 512);    // [64]

    const __half* qsrc = g_qh + ((size_t)bh * Ss + q0) * Dd;
    const __half* ksrc = g_kh + (size_t)bh * Ss * Dd;
    const __half* vsrc = g_vh + (size_t)bh * Ss * Dd;
    const unsigned char* msrc = g_m8 + (size_t)b * Ss * Ss + (size_t)q0 * Ss;
    __half* usrc = g_uh + ((size_t)bh * Ss + q0) * Ss;
    float* attg = att ? (att + (size_t)bh * Ss * (size_t)Ss) : nullptr;

    const int r0 = rgrp * 16 + g;
    const int r1 = r0 + 8;

    // per-thread cp.async addresses
    const int lr_ = tid >> 3, lc = tid & 7;          // K/V pattern: 32 rows x 8 chunks
    const int ur  = tid >> 4, uc = tid & 15;         // U pattern:   16 rows x 16 chunks
    const uint32_t kdstA = smb + OFF_K + lr_ * 144 + lc * 16;
    const uint32_t kdstB = kdstA + KSTG;
    const uint32_t vdstA = smb + OFF_V + lr_ * 144 + lc * 16;
    const uint32_t vdstB = vdstA + KSTG;
    const uint32_t mdstA = smb + OFF_M + lr_ * 144 + lc * 16;
    const uint32_t mdstB = mdstA + MSTG;
    const uint32_t udstA = smb + OFF_U + ur * 272 + uc * 16;
    const uint32_t udstB = udstA + USTG;
    const __half* ksrcT = ksrc + lr_ * 64 + lc * 8;
    const __half* vsrcT = vsrc + lr_ * 64 + lc * 8;
    const unsigned char* msrcT = msrc + (size_t)lr_ * Ss + lc * 16;
    const __half* usrcT = usrc + (size_t)ur * Ss + uc * 8;

    // fragment bases
    const uint32_t qfr  = smb + OFF_Q + (uint32_t)((rgrp * 16 + (lm & 1) * 8 + ll) * 144 + (lm >> 1) * 16);
    const uint32_t kfrA = smb + OFF_K + (uint32_t)((h * 64 + (lm >> 1) * 8 + ll) * 144 + (lm & 1) * 16);
    const uint32_t kfrB = kfrA + KSTG;
    const uint32_t vfrA = smb + OFF_V + (uint32_t)((h * 64 + (lm & 1) * 8 + ll) * 144 + (lm >> 1) * 16);
    const uint32_t vfrB = vfrA + KSTG;
    const uint32_t ufrA = smb + OFF_U + (uint32_t)((rgrp * 16 + (lm & 1) * 8 + ll) * 272 + h * 128 + (lm >> 1) * 16);
    const uint32_t ufrB = ufrA + USTG;
    const uint32_t mepA = smb + OFF_M + (uint32_t)(r0 * 144 + h * 64 + 2 * tg);
    const uint32_t mepB = mepA + MSTG;

    // ---- pass-1 prologue: Q + K0 + M0 ----
    CPA16(smb + OFF_Q + lr_ * 144 + lc * 16, qsrc + lr_ * 64 + lc * 8);
    CPA16(smb + OFF_Q + (lr_ + 32) * 144 + lc * 16, qsrc + (lr_ + 32) * 64 + lc * 8);
    CPA16(kdstA,         ksrcT);
    CPA16(kdstA +  4608, ksrcT + 2048);
    CPA16(kdstA +  9216, ksrcT + 4096);
    CPA16(kdstA + 13824, ksrcT + 6144);
    CPA16(mdstA,         msrcT);
    CPA16(mdstA + 4608,  msrcT + (size_t)32 * Ss);
    CP_COMMIT(); CP_WAIT0(); __syncthreads();

    uint32_t aQ[4][4];
    #pragma unroll
    for (int kc = 0; kc < 4; kc++) ldsm4(aQ[kc], qfr + kc * 32);

    // ================= PASS 1: row sums + u-fp16 store =================
    float rs0 = 0.f, rs1 = 0.f;
    {
        const __half* kpre = ksrcT + (size_t)KT * Dd;
        const unsigned char* mpre = msrcT + KT;
        __half* ug = usrc + (size_t)r0 * Ss + h * 64 + 2 * tg;
        #pragma unroll 1
        for (int t2 = 0; t2 < NT; t2 += 2) {
            P1_BODY(t2,     A, B);
            P1_BODY(t2 + 1, B, A);
        }
    }

    // reduce quad lanes, then the 2 col-halves; reciprocals
    rs0 += __shfl_xor_sync(0xffffffffu, rs0, 1); rs0 += __shfl_xor_sync(0xffffffffu, rs0, 2);
    rs1 += __shfl_xor_sync(0xffffffffu, rs1, 1); rs1 += __shfl_xor_sync(0xffffffffu, rs1, 2);
    if (tg == 0) { srows[h * 64 + r0] = rs0; srows[h * 64 + r1] = rs1; }
    __syncthreads();
    if (tid < 64) {
        float s = srows[tid] + srows[64 + tid];
        srinv[tid] = (s > 0.f) ? (1.0f / s) : 0.f;
    }
    __syncthreads();
    const float rv0 = srinv[r0];
    const float rv1 = srinv[r1];

    // ================= PASS 2: PV + scaled att writeout =================
    float o[8][4];
    #pragma unroll
    for (int j = 0; j < 8; j++) { o[j][0] = 0.f; o[j][1] = 0.f; o[j][2] = 0.f; o[j][3] = 0.f; }

    // prologue: U0 + V0
    CPA16(udstA,         usrcT);
    CPA16(udstA +  4352, usrcT + (size_t)16 * Ss);
    CPA16(udstA +  8704, usrcT + (size_t)32 * Ss);
    CPA16(udstA + 13056, usrcT + (size_t)48 * Ss);
    CPA16(vdstA,         vsrcT);
    CPA16(vdstA +  4608, vsrcT + 2048);
    CPA16(vdstA +  9216, vsrcT + 4096);
    CPA16(vdstA + 13824, vsrcT + 6144);
    CP_COMMIT(); CP_WAIT0(); __syncthreads();

    {
        const __half* upre = usrcT + KT;
        const __half* vpre = vsrcT + (size_t)KT * Dd;
        float* ar = attg ? (attg + (size_t)(q0 + r0) * Ss + h * 64 + 2 * tg) : nullptr;
        #pragma unroll 1
        for (int t2 = 0; t2 < NT; t2 += 2) {
            P2_BODY(t2,     A, B);
            P2_BODY(t2 + 1, B, A);
        }
    }

    // ---- combine the two k-halves of O via smem, scale by rinv, write ----
    __syncthreads();
    float* ost = (float*)(sm + OFF_U);            // [64][66]
    if (h == 1) {
        #pragma unroll
        for (int j = 0; j < 8; j++) {
            *(float2*)&ost[r0 * 66 + 8 * j + 2 * tg] = make_float2(o[j][0], o[j][1]);
            *(float2*)&ost[r1 * 66 + 8 * j + 2 * tg] = make_float2(o[j][2], o[j][3]);
        }
    }
    __syncthreads();
    if (out && h == 0) {
        float* og0 = out + ((size_t)bh * Ss + q0 + r0) * Dd;
        float* og1 = out + ((size_t)bh * Ss + q0 + r1) * Dd;
        #pragma unroll
        for (int j = 0; j < 8; j++) {
            float2 s0 = *(float2*)&ost[r0 * 66 + 8 * j + 2 * tg];
            float2 s1 = *(float2*)&ost[r1 * 66 + 8 * j + 2 * tg];
            *(float2*)(og0 + 8 * j + 2 * tg) = make_float2((o[j][0] + s0.x) * rv0, (o[j][1] + s0.y) * rv0);
            *(float2*)(og1 + 8 * j + 2 * tg) = make_float2((o[j][2] + s1.x) * rv1, (o[j][3] + s1.y) * rv1);
        }
    }
}

extern "C" void kernel_launch(void* const* d_in, const int* in_sizes, int n_in,
                              void* d_out, int out_size)
{
    (void)in_sizes; (void)n_in;
    const float* Q = (const float*)d_in[0];
    const float* K = (const float*)d_in[1];
    const float* V = (const float*)d_in[2];
    const int*   M = (const int*)d_in[3];

    float* outp = nullptr;
    float* attp = nullptr;
    long long os = (long long)out_size;
    if (os >= OUT_ELEMS + ATT_ELEMS) {
        outp = (float*)d_out;
        attp = (float*)d_out + OUT_ELEMS;
    } else if (os >= ATT_ELEMS) {
        attp = (float*)d_out;
    } else {
        outp = (float*)d_out;
    }

    cvt_all<<<QKV_BLOCKS + MASK_BLOCKS, 256>>>(Q, K, V, M);

    cudaFuncSetAttribute(attn_kernel, cudaFuncAttributeMaxDynamicSharedMemorySize, SMEM_BYTES);
    dim3 grid(Ss / QT, BH);
    attn_kernel<<<grid, NTH, SMEM_BYTES>>>(outp, attp);
}

// round 12
// speedup vs baseline: 1.2378x; 1.2134x over previous
#include <cuda_runtime.h>
#include <cuda_fp16.h>
#include <cstdint>

#define Ss 2048
#define Dd 64
constexpr int BH  = 32;
constexpr int QT  = 64;            // q rows per CTA
constexpr int KT  = 128;           // k cols per tile
constexpr int NTH = 256;           // 8 warps: 4 row-groups x 2 col-halves
constexpr int NT  = Ss / KT;       // 16
constexpr long long OUT_ELEMS = (long long)BH * Ss * Dd;
constexpr long long ATT_ELEMS = (long long)BH * Ss * (long long)Ss;

// static device scratch
__device__ __align__(256) __half g_qh[(size_t)BH * Ss * Dd];   // pre-scaled by log2e/8
__device__ __align__(256) __half g_kh[(size_t)BH * Ss * Dd];
__device__ __align__(256) __half g_vh[(size_t)BH * Ss * Dd];
__device__ __align__(256) uint32_t g_mb[(size_t)2 * Ss * Ss / 32];   // bit-packed mask (1MB)
__device__ __align__(256) uint32_t g_u32[(size_t)ATT_ELEMS / 2];     // u relay, fragment layout

// smem layout (bytes)
constexpr int OFF_RED = 0;                        // srows[2][64] + srinv[64] (768B)
constexpr int OFF_Q   = 1024;                     // P1: 64 x 144 = 9216
constexpr int KSTG    = 128 * 144;                // 18432
constexpr int OFF_K   = 10240;                    // P1: 2 stages -> 47104
constexpr int USTG    = 4 * 256 * 16;             // 16384 ([kc][tid][16B])
constexpr int OFF_U   = 1024;                     // P2 overlay: 2 stages -> 33792
constexpr int OFF_V   = 33792;                    // P2: 2 stages -> 70656
constexpr int SMEM_BYTES = 70656;                 // 3 CTAs/SM (P1 needs 47104)

__device__ __forceinline__ uint32_t smem_u32(const void* p) {
    uint32_t a;
    asm("{ .reg .u64 t; cvta.to.shared.u64 t, %1; cvt.u32.u64 %0, t; }" : "=r"(a) : "l"(p));
    return a;
}
__device__ __forceinline__ void ldsm4(uint32_t r[4], uint32_t a) {
    asm volatile("ldmatrix.sync.aligned.m8n8.x4.shared.b16 {%0,%1,%2,%3}, [%4];"
                 : "=r"(r[0]), "=r"(r[1]), "=r"(r[2]), "=r"(r[3]) : "r"(a) : "memory");
}
__device__ __forceinline__ void ldsm4t(uint32_t r[4], uint32_t a) {
    asm volatile("ldmatrix.sync.aligned.m8n8.x4.trans.shared.b16 {%0,%1,%2,%3}, [%4];"
                 : "=r"(r[0]), "=r"(r[1]), "=r"(r[2]), "=r"(r[3]) : "r"(a) : "memory");
}
__device__ __forceinline__ void lds128(uint32_t r[4], uint32_t a) {
    asm volatile("ld.shared.v4.u32 {%0,%1,%2,%3}, [%4];"
                 : "=r"(r[0]), "=r"(r[1]), "=r"(r[2]), "=r"(r[3]) : "r"(a) : "memory");
}
__device__ __forceinline__ void mma16816(float c[4], const uint32_t a[4], uint32_t b0, uint32_t b1) {
    asm volatile(
        "mma.sync.aligned.m16n8k16.row.col.f32.f16.f16.f32 "
        "{%0,%1,%2,%3}, {%4,%5,%6,%7}, {%8,%9}, {%0,%1,%2,%3};"
        : "+f"(c[0]), "+f"(c[1]), "+f"(c[2]), "+f"(c[3])
        : "r"(a[0]), "r"(a[1]), "r"(a[2]), "r"(a[3]), "r"(b0), "r"(b1));
}
__device__ __forceinline__ uint32_t packh2(float x, float y) {
    __half2 h = __floats2half2_rn(x, y);
    return *(uint32_t*)&h;
}
__device__ __forceinline__ float ex2f(float x) {
    float r; asm("ex2.approx.f32 %0, %1;" : "=f"(r) : "f"(x)); return r;
}
#define CPA16(dst, src) asm volatile("cp.async.cg.shared.global [%0], [%1], 16;" :: "r"(dst), "l"(src))
#define CP_COMMIT()     asm volatile("cp.async.commit_group;" ::: "memory")
#define CP_WAIT0()      asm volatile("cp.async.wait_group 0;" ::: "memory")

constexpr int QKV_BLOCKS  = 3 * (BH * Ss * Dd / 4) / 256;       // 12288
constexpr int MBIT_BLOCKS = (2 * Ss * Ss / 32) / 256;           // 1024
constexpr float QSCALE = 0.18033688011112042f;                  // log2(e)/8

__global__ void __launch_bounds__(256) cvt_all(const float* __restrict__ Q,
                                               const float* __restrict__ K,
                                               const float* __restrict__ V,
                                               const int* __restrict__ M)
{
    if (blockIdx.x < QKV_BLOCKS) {
        const int n4 = BH * Ss * Dd / 4;
        int id = blockIdx.x * 256 + threadIdx.x;
        const float* src; __half* dst; float s;
        int i = id;
        if (id < n4)          { src = Q; dst = g_qh; s = QSCALE; }
        else if (id < 2 * n4) { src = K; dst = g_kh; s = 1.f; i -= n4; }
        else                  { src = V; dst = g_vh; s = 1.f; i -= 2 * n4; }
        float4 v = ((const float4*)src)[i];
        uint2 u; u.x = packh2(v.x * s, v.y * s); u.y = packh2(v.z * s, v.w * s);
        ((uint2*)dst)[i] = u;
    } else {
        int gid = (blockIdx.x - QKV_BLOCKS) * 256 + threadIdx.x;   // 262144 threads
        const int4* mp = (const int4*)M + (size_t)gid * 8;
        uint32_t bits = 0;
        #pragma unroll
        for (int j = 0; j < 8; j++) {
            int4 m = mp[j];
            bits |= (m.x ? 1u : 0u) << (4 * j);
            bits |= (m.y ? 1u : 0u) << (4 * j + 1);
            bits |= (m.z ? 1u : 0u) << (4 * j + 2);
            bits |= (m.w ? 1u : 0u) << (4 * j + 3);
        }
        g_mb[gid] = bits;
    }
}

extern __shared__ __align__(16) char sm[];

// ---------------- pass 1 tile body ----------------
#define P1_BODY(T, CUR, NXT) do {                                          \
    if ((T) + 1 < NT) {                                                    \
        CPA16(kdst##NXT,         kpre);                                    \
        CPA16(kdst##NXT +  4608, kpre + 2048);                             \
        CPA16(kdst##NXT +  9216, kpre + 4096);                             \
        CPA16(kdst##NXT + 13824, kpre + 6144);                             \
        CP_COMMIT();                                                       \
        kpre += (size_t)KT * Dd;                                           \
        mn0 = mr0[2 * ((T) + 1)];                                          \
        mn1 = mr1[2 * ((T) + 1)];                                          \
    }                                                                      \
    _Pragma("unroll") for (int ch = 0; ch < 2; ch++) {                     \
        float c4[4][4];                                                    \
        _Pragma("unroll") for (int j = 0; j < 4; j++) {                    \
            c4[j][0] = 0.f; c4[j][1] = 0.f; c4[j][2] = 0.f; c4[j][3] = 0.f; } \
        _Pragma("unroll") for (int kc = 0; kc < 4; kc++)                   \
            _Pragma("unroll") for (int j = 0; j < 2; j++) {                \
                uint32_t bf[4];                                            \
                ldsm4(bf, kfr##CUR + (2 * ch + j) * 2304 + kc * 32);       \
                mma16816(c4[2 * j],     aQ[kc], bf[0], bf[1]);             \
                mma16816(c4[2 * j + 1], aQ[kc], bf[2], bf[3]);             \
            }                                                              \
        uint32_t ul[4], uh[4];                                             \
        _Pragma("unroll") for (int j = 0; j < 4; j++) {                    \
            const int p = 8 * (4 * ch + j) + 2 * tg;                       \
            uint32_t b0 = (uint32_t)(mc0 >> p), b1 = (uint32_t)(mc1 >> p); \
            float u0 = (b0 & 1u) ? ex2f(c4[j][0]) : 0.f;                   \
            float u1 = (b0 & 2u) ? ex2f(c4[j][1]) : 0.f;                   \
            float u2 = (b1 & 1u) ? ex2f(c4[j][2]) : 0.f;                   \
            float u3 = (b1 & 2u) ? ex2f(c4[j][3]) : 0.f;                   \
            rs0 += u0 + u1; rs1 += u2 + u3;                                \
            ul[j] = packh2(u0, u1); uh[j] = packh2(u2, u3);                \
        }                                                                  \
        *(uint4*)(ut + (2 * ch) * 1024)     = make_uint4(ul[0], uh[0], ul[1], uh[1]); \
        *(uint4*)(ut + (2 * ch + 1) * 1024) = make_uint4(ul[2], uh[2], ul[3], uh[3]); \
    }                                                                      \
    ut += 4096;                                                            \
    mc0 = mn0; mc1 = mn1;                                                  \
    if ((T) + 1 < NT) { CP_WAIT0(); __syncthreads(); }                     \
} while (0)

// ---------------- pass 2 tile body ----------------
#define P2_BODY(T, CUR, NXT) do {                                          \
    if ((T) + 1 < NT) {                                                    \
        CPA16(udst##NXT,         upre);                                    \
        CPA16(udst##NXT +  4096, upre + 4096);                             \
        CPA16(udst##NXT +  8192, upre + 8192);                             \
        CPA16(udst##NXT + 12288, upre + 12288);                            \
        CPA16(vdst##NXT,         vpre);                                    \
        CPA16(vdst##NXT +  4608, vpre + 2048);                             \
        CPA16(vdst##NXT +  9216, vpre + 4096);                             \
        CPA16(vdst##NXT + 13824, vpre + 6144);                             \
        CP_COMMIT();                                                       \
        upre += 16384; vpre += (size_t)KT * Dd;                            \
    }                                                                      \
    _Pragma("unroll") for (int kc = 0; kc < 4; kc++) {                     \
        uint32_t a[4];                                                     \
        lds128(a, uld##CUR + kc * 4096);                                   \
        _Pragma("unroll") for (int np = 0; np < 4; np++) {                 \
            uint32_t bf[4];                                                \
            ldsm4t(bf, vfr##CUR + kc * 2304 + np * 32);                    \
            mma16816(o[2 * np],     a, bf[0], bf[1]);                      \
            mma16816(o[2 * np + 1], a, bf[2], bf[3]);                      \
        }                                                                  \
        if (ar) {                                                          \
            float2 f0 = __half22float2(*(__half2*)&a[0]);                  \
            float2 f1 = __half22float2(*(__half2*)&a[1]);                  \
            float2 f2 = __half22float2(*(__half2*)&a[2]);                  \
            float2 f3 = __half22float2(*(__half2*)&a[3]);                  \
            *(float2*)(ar + 16 * kc)              = make_float2(f0.x * rv0, f0.y * rv0); \
            *(float2*)(ar + 8 * Ss + 16 * kc)     = make_float2(f1.x * rv1, f1.y * rv1); \
            *(float2*)(ar + 16 * kc + 8)          = make_float2(f2.x * rv0, f2.y * rv0); \
            *(float2*)(ar + 8 * Ss + 16 * kc + 8) = make_float2(f3.x * rv1, f3.y * rv1); \
        }                                                                  \
    }                                                                      \
    if (ar) ar += KT;                                                      \
    if ((T) + 1 < NT) { CP_WAIT0(); __syncthreads(); }                     \
} while (0)

__global__ void __launch_bounds__(NTH, 3)
attn_kernel(float* __restrict__ out, float* __restrict__ att)
{
    const int tid  = threadIdx.x;
    const int lane = tid & 31;
    const int warp = tid >> 5;
    const int g    = lane >> 2;
    const int tg   = lane & 3;
    const int lm   = lane >> 3;
    const int ll   = lane & 7;
    const int rgrp = warp & 3;         // q-row group (16 rows)
    const int h    = warp >> 2;        // k-col half (64 cols)

    const int qblk = blockIdx.x;
    const int q0 = qblk * QT;
    const int bh = blockIdx.y;
    const int b  = bh >> 4;

    const uint32_t smb = smem_u32(sm);
    float* srows = (float*)(sm + OFF_RED);          // [2][64]
    float* srinv = (float*)(sm + OFF_RED + 512);    // [64]

    const __half* qsrc = g_qh + ((size_t)bh * Ss + q0) * Dd;
    const __half* ksrc = g_kh + (size_t)bh * Ss * Dd;
    const __half* vsrc = g_vh + (size_t)bh * Ss * Dd;
    float* attg = att ? (att + (size_t)bh * Ss * (size_t)Ss) : nullptr;

    const int r0 = rgrp * 16 + g;
    const int r1 = r0 + 8;

    // bit-mask row pointers (u64 per 64 cols; row stride = 32 u64)
    const unsigned long long* mb64 = (const unsigned long long*)g_mb;
    const unsigned long long* mr0 = mb64 + ((size_t)b * Ss + q0 + r0) * 32 + h;
    const unsigned long long* mr1 = mr0 + 8 * 32;

    // u relay pointers (fragment layout: [tile][kc][tid][4 u32])
    uint32_t* ut = g_u32 + (((size_t)bh * 32 + qblk) * 16) * 4096 + tid * 4;
    const char* ub = (const char*)(g_u32 + (((size_t)bh * 32 + qblk) * 16) * 4096) + tid * 16;

    // per-thread cp.async addresses
    const int lr_ = tid >> 3, lc = tid & 7;          // K/V pattern: 32 rows x 8 chunks
    const uint32_t kdstA = smb + OFF_K + lr_ * 144 + lc * 16;
    const uint32_t kdstB = kdstA + KSTG;
    const uint32_t vdstA = smb + OFF_V + lr_ * 144 + lc * 16;
    const uint32_t vdstB = vdstA + KSTG;
    const uint32_t udstA = smb + OFF_U + tid * 16;
    const uint32_t udstB = udstA + USTG;
    const __half* ksrcT = ksrc + lr_ * 64 + lc * 8;
    const __half* vsrcT = vsrc + lr_ * 64 + lc * 8;

    // fragment bases
    const uint32_t qfr  = smb + OFF_Q + (uint32_t)((rgrp * 16 + (lm & 1) * 8 + ll) * 144 + (lm >> 1) * 16);
    const uint32_t kfrA = smb + OFF_K + (uint32_t)((h * 64 + (lm >> 1) * 8 + ll) * 144 + (lm & 1) * 16);
    const uint32_t kfrB = kfrA + KSTG;
    const uint32_t vfrA = smb + OFF_V + (uint32_t)((h * 64 + (lm & 1) * 8 + ll) * 144 + (lm >> 1) * 16);
    const uint32_t vfrB = vfrA + KSTG;
    const uint32_t uldA = smb + OFF_U + tid * 16;
    const uint32_t uldB = uldA + USTG;

    // ---- pass-1 prologue: Q + K0 ----
    CPA16(smb + OFF_Q + lr_ * 144 + lc * 16, qsrc + lr_ * 64 + lc * 8);
    CPA16(smb + OFF_Q + (lr_ + 32) * 144 + lc * 16, qsrc + (lr_ + 32) * 64 + lc * 8);
    CPA16(kdstA,         ksrcT);
    CPA16(kdstA +  4608, ksrcT + 2048);
    CPA16(kdstA +  9216, ksrcT + 4096);
    CPA16(kdstA + 13824, ksrcT + 6144);
    CP_COMMIT();
    unsigned long long mc0 = mr0[0], mc1 = mr1[0], mn0 = 0, mn1 = 0;
    CP_WAIT0(); __syncthreads();

    uint32_t aQ[4][4];
    #pragma unroll
    for (int kc = 0; kc < 4; kc++) ldsm4(aQ[kc], qfr + kc * 32);

    // ================= PASS 1: row sums + u relay store =================
    float rs0 = 0.f, rs1 = 0.f;
    {
        const __half* kpre = ksrcT + (size_t)KT * Dd;
        #pragma unroll 1
        for (int t2 = 0; t2 < NT; t2 += 2) {
            P1_BODY(t2,     A, B);
            P1_BODY(t2 + 1, B, A);
        }
    }

    // reduce quad lanes, then the 2 col-halves; reciprocals
    rs0 += __shfl_xor_sync(0xffffffffu, rs0, 1); rs0 += __shfl_xor_sync(0xffffffffu, rs0, 2);
    rs1 += __shfl_xor_sync(0xffffffffu, rs1, 1); rs1 += __shfl_xor_sync(0xffffffffu, rs1, 2);
    if (tg == 0) { srows[h * 64 + r0] = rs0; srows[h * 64 + r1] = rs1; }
    __syncthreads();
    if (tid < 64) {
        float s = srows[tid] + srows[64 + tid];
        srinv[tid] = (s > 0.f) ? (1.0f / s) : 0.f;
    }
    __syncthreads();
    const float rv0 = srinv[r0];
    const float rv1 = srinv[r1];

    // ================= PASS 2: PV + scaled att writeout =================
    float o[8][4];
    #pragma unroll
    for (int j = 0; j < 8; j++) { o[j][0] = 0.f; o[j][1] = 0.f; o[j][2] = 0.f; o[j][3] = 0.f; }

    // prologue: U0 + V0 -> stage A
    CPA16(udstA,         ub);
    CPA16(udstA +  4096, ub + 4096);
    CPA16(udstA +  8192, ub + 8192);
    CPA16(udstA + 12288, ub + 12288);
    CPA16(vdstA,         vsrcT);
    CPA16(vdstA +  4608, vsrcT + 2048);
    CPA16(vdstA +  9216, vsrcT + 4096);
    CPA16(vdstA + 13824, vsrcT + 6144);
    CP_COMMIT(); CP_WAIT0(); __syncthreads();

    {
        const char* upre = ub + 16384;
        const __half* vpre = vsrcT + (size_t)KT * Dd;
        float* ar = attg ? (attg + (size_t)(q0 + r0) * Ss + h * 64 + 2 * tg) : nullptr;
        #pragma unroll 1
        for (int t2 = 0; t2 < NT; t2 += 2) {
            P2_BODY(t2,     A, B);
            P2_BODY(t2 + 1, B, A);
        }
    }

    // ---- combine the two k-halves of O via smem, scale by rinv, write ----
    __syncthreads();
    float* ost = (float*)(sm + OFF_U);            // [64][66]
    if (h == 1) {
        #pragma unroll
        for (int j = 0; j < 8; j++) {
            *(float2*)&ost[r0 * 66 + 8 * j + 2 * tg] = make_float2(o[j][0], o[j][1]);
            *(float2*)&ost[r1 * 66 + 8 * j + 2 * tg] = make_float2(o[j][2], o[j][3]);
        }
    }
    __syncthreads();
    if (out && h == 0) {
        float* og0 = out + ((size_t)bh * Ss + q0 + r0) * Dd;
        float* og1 = out + ((size_t)bh * Ss + q0 + r1) * Dd;
        #pragma unroll
        for (int j = 0; j < 8; j++) {
            float2 s0 = *(float2*)&ost[r0 * 66 + 8 * j + 2 * tg];
            float2 s1 = *(float2*)&ost[r1 * 66 + 8 * j + 2 * tg];
            *(float2*)(og0 + 8 * j + 2 * tg) = make_float2((o[j][0] + s0.x) * rv0, (o[j][1] + s0.y) * rv0);
            *(float2*)(og1 + 8 * j + 2 * tg) = make_float2((o[j][2] + s1.x) * rv1, (o[j][3] + s1.y) * rv1);
        }
    }
}

extern "C" void kernel_launch(void* const* d_in, const int* in_sizes, int n_in,
                              void* d_out, int out_size)
{
    (void)in_sizes; (void)n_in;
    const float* Q = (const float*)d_in[0];
    const float* K = (const float*)d_in[1];
    const float* V = (const float*)d_in[2];
    const int*   M = (const int*)d_in[3];

    float* outp = nullptr;
    float* attp = nullptr;
    long long os = (long long)out_size;
    if (os >= OUT_ELEMS + ATT_ELEMS) {
        outp = (float*)d_out;
        attp = (float*)d_out + OUT_ELEMS;
    } else if (os >= ATT_ELEMS) {
        attp = (float*)d_out;
    } else {
        outp = (float*)d_out;
    }

    cvt_all<<<QKV_BLOCKS + MBIT_BLOCKS, 256>>>(Q, K, V, M);

    cudaFuncSetAttribute(attn_kernel, cudaFuncAttributeMaxDynamicSharedMemorySize, SMEM_BYTES);
    dim3 grid(Ss / QT, BH);
    attn_kernel<<<grid, NTH, SMEM_BYTES>>>(outp, attp);
}

// round 13
// speedup vs baseline: 1.2604x; 1.0182x over previous
#include <cuda_runtime.h>
#include <cuda_fp16.h>
#include <cstdint>

#define Ss 2048
#define Dd 64
constexpr int BH  = 32;
constexpr int QT  = 64;            // q rows per CTA
constexpr int KT  = 128;           // k cols per tile
constexpr int NTH = 256;           // 8 warps: 4 row-groups x 2 col-halves
constexpr int NT  = Ss / KT;       // 16
constexpr long long OUT_ELEMS = (long long)BH * Ss * Dd;
constexpr long long ATT_ELEMS = (long long)BH * Ss * (long long)Ss;

// static device scratch
__device__ __align__(256) __half g_qh[(size_t)BH * Ss * Dd];   // pre-scaled by log2e/8
__device__ __align__(256) __half g_kh[(size_t)BH * Ss * Dd];
__device__ __align__(256) __half g_vh[(size_t)BH * Ss * Dd];
__device__ __align__(256) uint32_t g_mb[(size_t)2 * Ss * Ss / 32];   // bit-packed mask (1MB)
__device__ __align__(256) uint32_t g_u32[(size_t)ATT_ELEMS / 2];     // u relay, fragment layout

// smem layout (bytes)
constexpr int OFF_RED = 0;                        // srows[2][64] + srinv[64] (768B)
constexpr int OFF_Q   = 1024;                     // P1: 64 x 144 = 9216
constexpr int KSTG    = 128 * 144;                // 18432
constexpr int OFF_K   = 10240;                    // P1: 2 stages -> 47104
constexpr int OFF_V   = 1024;                     // P2 overlay: 2 stages -> 37888
constexpr int SMEM_BYTES = 47104;                 // 3 CTAs/SM

__device__ __forceinline__ uint32_t smem_u32(const void* p) {
    uint32_t a;
    asm("{ .reg .u64 t; cvta.to.shared.u64 t, %1; cvt.u32.u64 %0, t; }" : "=r"(a) : "l"(p));
    return a;
}
__device__ __forceinline__ void ldsm4(uint32_t r[4], uint32_t a) {
    asm volatile("ldmatrix.sync.aligned.m8n8.x4.shared.b16 {%0,%1,%2,%3}, [%4];"
                 : "=r"(r[0]), "=r"(r[1]), "=r"(r[2]), "=r"(r[3]) : "r"(a) : "memory");
}
__device__ __forceinline__ void ldsm4t(uint32_t r[4], uint32_t a) {
    asm volatile("ldmatrix.sync.aligned.m8n8.x4.trans.shared.b16 {%0,%1,%2,%3}, [%4];"
                 : "=r"(r[0]), "=r"(r[1]), "=r"(r[2]), "=r"(r[3]) : "r"(a) : "memory");
}
__device__ __forceinline__ void mma16816(float c[4], const uint32_t a[4], uint32_t b0, uint32_t b1) {
    asm volatile(
        "mma.sync.aligned.m16n8k16.row.col.f32.f16.f16.f32 "
        "{%0,%1,%2,%3}, {%4,%5,%6,%7}, {%8,%9}, {%0,%1,%2,%3};"
        : "+f"(c[0]), "+f"(c[1]), "+f"(c[2]), "+f"(c[3])
        : "r"(a[0]), "r"(a[1]), "r"(a[2]), "r"(a[3]), "r"(b0), "r"(b1));
}
__device__ __forceinline__ uint32_t packh2(float x, float y) {
    __half2 h = __floats2half2_rn(x, y);
    return *(uint32_t*)&h;
}
__device__ __forceinline__ float ex2f(float x) {
    float r; asm("ex2.approx.f32 %0, %1;" : "=f"(r) : "f"(x)); return r;
}
#define CPA16(dst, src) asm volatile("cp.async.cg.shared.global [%0], [%1], 16;" :: "r"(dst), "l"(src))
#define CP_COMMIT()     asm volatile("cp.async.commit_group;" ::: "memory")
#define CP_WAIT0()      asm volatile("cp.async.wait_group 0;" ::: "memory")
#define STG64CS(p, x, y) \
    asm volatile("st.global.cs.v2.f32 [%0], {%1,%2};" :: "l"(p), "f"(x), "f"(y) : "memory")

constexpr int QKV_BLOCKS  = 3 * (BH * Ss * Dd / 4) / 256;       // 12288
constexpr int MBIT_BLOCKS = (2 * Ss * Ss / 32) / 256;           // 1024
constexpr float QSCALE = 0.18033688011112042f;                  // log2(e)/8

__global__ void __launch_bounds__(256) cvt_all(const float* __restrict__ Q,
                                               const float* __restrict__ K,
                                               const float* __restrict__ V,
                                               const int* __restrict__ M)
{
    if (blockIdx.x < QKV_BLOCKS) {
        const int n4 = BH * Ss * Dd / 4;
        int id = blockIdx.x * 256 + threadIdx.x;
        const float* src; __half* dst; float s;
        int i = id;
        if (id < n4)          { src = Q; dst = g_qh; s = QSCALE; }
        else if (id < 2 * n4) { src = K; dst = g_kh; s = 1.f; i -= n4; }
        else                  { src = V; dst = g_vh; s = 1.f; i -= 2 * n4; }
        float4 v = ((const float4*)src)[i];
        uint2 u; u.x = packh2(v.x * s, v.y * s); u.y = packh2(v.z * s, v.w * s);
        ((uint2*)dst)[i] = u;
    } else {
        int gid = (blockIdx.x - QKV_BLOCKS) * 256 + threadIdx.x;   // 262144 threads
        const int4* mp = (const int4*)M + (size_t)gid * 8;
        uint32_t bits = 0;
        #pragma unroll
        for (int j = 0; j < 8; j++) {
            int4 m = mp[j];
            bits |= (m.x ? 1u : 0u) << (4 * j);
            bits |= (m.y ? 1u : 0u) << (4 * j + 1);
            bits |= (m.z ? 1u : 0u) << (4 * j + 2);
            bits |= (m.w ? 1u : 0u) << (4 * j + 3);
        }
        g_mb[gid] = bits;
    }
}

extern __shared__ __align__(16) char sm[];

// ---------------- pass 1 tile body ----------------
#define P1_BODY(T, CUR, NXT) do {                                          \
    if ((T) + 1 < NT) {                                                    \
        CPA16(kdst##NXT,         kpre);                                    \
        CPA16(kdst##NXT +  4608, kpre + 2048);                             \
        CPA16(kdst##NXT +  9216, kpre + 4096);                             \
        CPA16(kdst##NXT + 13824, kpre + 6144);                             \
        CP_COMMIT();                                                       \
        kpre += (size_t)KT * Dd;                                           \
        mn0 = __ldg(mr0 + 2 * ((T) + 1));                                  \
        mn1 = __ldg(mr1 + 2 * ((T) + 1));                                  \
    }                                                                      \
    _Pragma("unroll") for (int ch = 0; ch < 2; ch++) {                     \
        float c4[4][4];                                                    \
        _Pragma("unroll") for (int j = 0; j < 4; j++) {                    \
            c4[j][0] = 0.f; c4[j][1] = 0.f; c4[j][2] = 0.f; c4[j][3] = 0.f; } \
        _Pragma("unroll") for (int kc = 0; kc < 4; kc++)                   \
            _Pragma("unroll") for (int j = 0; j < 2; j++) {                \
                uint32_t bf[4];                                            \
                ldsm4(bf, kfr##CUR + (2 * ch + j) * 2304 + kc * 32);       \
                mma16816(c4[2 * j],     aQ[kc], bf[0], bf[1]);             \
                mma16816(c4[2 * j + 1], aQ[kc], bf[2], bf[3]);             \
            }                                                              \
        uint32_t ul[4], uh[4];                                             \
        _Pragma("unroll") for (int j = 0; j < 4; j++) {                    \
            const int p = 8 * (4 * ch + j) + 2 * tg;                       \
            uint32_t b0 = (uint32_t)(mc0 >> p), b1 = (uint32_t)(mc1 >> p); \
            float u0 = (b0 & 1u) ? ex2f(c4[j][0]) : 0.f;                   \
            float u1 = (b0 & 2u) ? ex2f(c4[j][1]) : 0.f;                   \
            float u2 = (b1 & 1u) ? ex2f(c4[j][2]) : 0.f;                   \
            float u3 = (b1 & 2u) ? ex2f(c4[j][3]) : 0.f;                   \
            rs0 += u0 + u1; rs1 += u2 + u3;                                \
            ul[j] = packh2(u0, u1); uh[j] = packh2(u2, u3);                \
        }                                                                  \
        *(uint4*)(ut + (2 * ch) * 1024)     = make_uint4(ul[0], uh[0], ul[1], uh[1]); \
        *(uint4*)(ut + (2 * ch + 1) * 1024) = make_uint4(ul[2], uh[2], ul[3], uh[3]); \
    }                                                                      \
    ut += 4096;                                                            \
    mc0 = mn0; mc1 = mn1;                                                  \
    if ((T) + 1 < NT) { CP_WAIT0(); __syncthreads(); }                     \
} while (0)

// ---------------- pass 2 tile body (u via direct LDG.128, frag layout) ----------------
#define P2_BODY(T, CUR, NXT) do {                                          \
    uint4 ua[4];                                                           \
    ua[0] = __ldg((const uint4*)(upr));                                    \
    ua[1] = __ldg((const uint4*)(upr + 4096));                             \
    ua[2] = __ldg((const uint4*)(upr + 8192));                             \
    ua[3] = __ldg((const uint4*)(upr + 12288));                            \
    upr += 16384;                                                          \
    if ((T) + 1 < NT) {                                                    \
        CPA16(vdst##NXT,         vpre);                                    \
        CPA16(vdst##NXT +  4608, vpre + 2048);                             \
        CPA16(vdst##NXT +  9216, vpre + 4096);                             \
        CPA16(vdst##NXT + 13824, vpre + 6144);                             \
        CP_COMMIT();                                                       \
        vpre += (size_t)KT * Dd;                                           \
    }                                                                      \
    _Pragma("unroll") for (int kc = 0; kc < 4; kc++) {                     \
        uint32_t a[4] = { ua[kc].x, ua[kc].y, ua[kc].z, ua[kc].w };        \
        _Pragma("unroll") for (int np = 0; np < 4; np++) {                 \
            uint32_t bf[4];                                                \
            ldsm4t(bf, vfr##CUR + kc * 2304 + np * 32);                    \
            mma16816(o[2 * np],     a, bf[0], bf[1]);                      \
            mma16816(o[2 * np + 1], a, bf[2], bf[3]);                      \
        }                                                                  \
        if (ar) {                                                          \
            float2 f0 = __half22float2(*(__half2*)&a[0]);                  \
            float2 f1 = __half22float2(*(__half2*)&a[1]);                  \
            float2 f2 = __half22float2(*(__half2*)&a[2]);                  \
            float2 f3 = __half22float2(*(__half2*)&a[3]);                  \
            STG64CS(ar + 16 * kc,              f0.x * rv0, f0.y * rv0);    \
            STG64CS(ar + 8 * Ss + 16 * kc,     f1.x * rv1, f1.y * rv1);    \
            STG64CS(ar + 16 * kc + 8,          f2.x * rv0, f2.y * rv0);    \
            STG64CS(ar + 8 * Ss + 16 * kc + 8, f3.x * rv1, f3.y * rv1);    \
        }                                                                  \
    }                                                                      \
    if (ar) ar += KT;                                                      \
    if ((T) + 1 < NT) { CP_WAIT0(); __syncthreads(); }                     \
} while (0)

__global__ void __launch_bounds__(NTH, 3)
attn_kernel(float* __restrict__ out, float* __restrict__ att)
{
    const int tid  = threadIdx.x;
    const int lane = tid & 31;
    const int warp = tid >> 5;
    const int g    = lane >> 2;
    const int tg   = lane & 3;
    const int lm   = lane >> 3;
    const int ll   = lane & 7;
    const int rgrp = warp & 3;         // q-row group (16 rows)
    const int h    = warp >> 2;        // k-col half (64 cols)

    const int qblk = blockIdx.x;
    const int q0 = qblk * QT;
    const int bh = blockIdx.y;
    const int b  = bh >> 4;

    const uint32_t smb = smem_u32(sm);
    float* srows = (float*)(sm + OFF_RED);          // [2][64]
    float* srinv = (float*)(sm + OFF_RED + 512);    // [64]

    const __half* qsrc = g_qh + ((size_t)bh * Ss + q0) * Dd;
    const __half* ksrc = g_kh + (size_t)bh * Ss * Dd;
    const __half* vsrc = g_vh + (size_t)bh * Ss * Dd;
    float* attg = att ? (att + (size_t)bh * Ss * (size_t)Ss) : nullptr;

    const int r0 = rgrp * 16 + g;
    const int r1 = r0 + 8;

    // bit-mask row pointers (u64 per 64 cols; row stride = 32 u64)
    const unsigned long long* mb64 = (const unsigned long long*)g_mb;
    const unsigned long long* mr0 = mb64 + ((size_t)b * Ss + q0 + r0) * 32 + h;
    const unsigned long long* mr1 = mr0 + 8 * 32;

    // u relay pointers (fragment layout: [tile][kc][tid][4 u32])
    uint32_t* ut = g_u32 + (((size_t)bh * 32 + qblk) * 16) * 4096 + tid * 4;
    const char* upr = (const char*)(g_u32 + (((size_t)bh * 32 + qblk) * 16) * 4096) + tid * 16;

    // per-thread cp.async addresses
    const int lr_ = tid >> 3, lc = tid & 7;          // K/V pattern: 32 rows x 8 chunks
    const uint32_t kdstA = smb + OFF_K + lr_ * 144 + lc * 16;
    const uint32_t kdstB = kdstA + KSTG;
    const uint32_t vdstA = smb + OFF_V + lr_ * 144 + lc * 16;
    const uint32_t vdstB = vdstA + KSTG;
    const __half* ksrcT = ksrc + lr_ * 64 + lc * 8;
    const __half* vsrcT = vsrc + lr_ * 64 + lc * 8;

    // fragment bases
    const uint32_t qfr  = smb + OFF_Q + (uint32_t)((rgrp * 16 + (lm & 1) * 8 + ll) * 144 + (lm >> 1) * 16);
    const uint32_t kfrA = smb + OFF_K + (uint32_t)((h * 64 + (lm >> 1) * 8 + ll) * 144 + (lm & 1) * 16);
    const uint32_t kfrB = kfrA + KSTG;
    const uint32_t vfrA = smb + OFF_V + (uint32_t)((h * 64 + (lm & 1) * 8 + ll) * 144 + (lm >> 1) * 16);
    const uint32_t vfrB = vfrA + KSTG;

    // ---- pass-1 prologue: Q + K0 ----
    CPA16(smb + OFF_Q + lr_ * 144 + lc * 16, qsrc + lr_ * 64 + lc * 8);
    CPA16(smb + OFF_Q + (lr_ + 32) * 144 + lc * 16, qsrc + (lr_ + 32) * 64 + lc * 8);
    CPA16(kdstA,         ksrcT);
    CPA16(kdstA +  4608, ksrcT + 2048);
    CPA16(kdstA +  9216, ksrcT + 4096);
    CPA16(kdstA + 13824, ksrcT + 6144);
    CP_COMMIT();
    unsigned long long mc0 = __ldg(mr0), mc1 = __ldg(mr1), mn0 = 0, mn1 = 0;
    CP_WAIT0(); __syncthreads();

    uint32_t aQ[4][4];
    #pragma unroll
    for (int kc = 0; kc < 4; kc++) ldsm4(aQ[kc], qfr + kc * 32);

    // ================= PASS 1: row sums + u relay store =================
    float rs0 = 0.f, rs1 = 0.f;
    {
        const __half* kpre = ksrcT + (size_t)KT * Dd;
        #pragma unroll 1
        for (int t2 = 0; t2 < NT; t2 += 2) {
            P1_BODY(t2,     A, B);
            P1_BODY(t2 + 1, B, A);
        }
    }

    // reduce quad lanes, then the 2 col-halves; reciprocals
    rs0 += __shfl_xor_sync(0xffffffffu, rs0, 1); rs0 += __shfl_xor_sync(0xffffffffu, rs0, 2);
    rs1 += __shfl_xor_sync(0xffffffffu, rs1, 1); rs1 += __shfl_xor_sync(0xffffffffu, rs1, 2);
    if (tg == 0) { srows[h * 64 + r0] = rs0; srows[h * 64 + r1] = rs1; }
    __syncthreads();
    if (tid < 64) {
        float s = srows[tid] + srows[64 + tid];
        srinv[tid] = (s > 0.f) ? (1.0f / s) : 0.f;
    }
    __syncthreads();
    const float rv0 = srinv[r0];
    const float rv1 = srinv[r1];
    __syncthreads();          // all reads of reduction smem done before V overlays it

    // ================= PASS 2: PV + scaled att writeout =================
    float o[8][4];
    #pragma unroll
    for (int j = 0; j < 8; j++) { o[j][0] = 0.f; o[j][1] = 0.f; o[j][2] = 0.f; o[j][3] = 0.f; }

    // prologue: V0 -> stage A
    CPA16(vdstA,         vsrcT);
    CPA16(vdstA +  4608, vsrcT + 2048);
    CPA16(vdstA +  9216, vsrcT + 4096);
    CPA16(vdstA + 13824, vsrcT + 6144);
    CP_COMMIT(); CP_WAIT0(); __syncthreads();

    {
        const __half* vpre = vsrcT + (size_t)KT * Dd;
        float* ar = attg ? (attg + (size_t)(q0 + r0) * Ss + h * 64 + 2 * tg) : nullptr;
        #pragma unroll 1
        for (int t2 = 0; t2 < NT; t2 += 2) {
            P2_BODY(t2,     A, B);
            P2_BODY(t2 + 1, B, A);
        }
    }

    // ---- combine the two k-halves of O via smem, scale by rinv, write ----
    __syncthreads();
    float* ost = (float*)(sm + OFF_V);            // [64][66]
    if (h == 1) {
        #pragma unroll
        for (int j = 0; j < 8; j++) {
            *(float2*)&ost[r0 * 66 + 8 * j + 2 * tg] = make_float2(o[j][0], o[j][1]);
            *(float2*)&ost[r1 * 66 + 8 * j + 2 * tg] = make_float2(o[j][2], o[j][3]);
        }
    }
    __syncthreads();
    if (out && h == 0) {
        float* og0 = out + ((size_t)bh * Ss + q0 + r0) * Dd;
        float* og1 = out + ((size_t)bh * Ss + q0 + r1) * Dd;
        #pragma unroll
        for (int j = 0; j < 8; j++) {
            float2 s0 = *(float2*)&ost[r0 * 66 + 8 * j + 2 * tg];
            float2 s1 = *(float2*)&ost[r1 * 66 + 8 * j + 2 * tg];
            *(float2*)(og0 + 8 * j + 2 * tg) = make_float2((o[j][0] + s0.x) * rv0, (o[j][1] + s0.y) * rv0);
            *(float2*)(og1 + 8 * j + 2 * tg) = make_float2((o[j][2] + s1.x) * rv1, (o[j][3] + s1.y) * rv1);
        }
    }
}

extern "C" void kernel_launch(void* const* d_in, const int* in_sizes, int n_in,
                              void* d_out, int out_size)
{
    (void)in_sizes; (void)n_in;
    const float* Q = (const float*)d_in[0];
    const float* K = (const float*)d_in[1];
    const float* V = (const float*)d_in[2];
    const int*   M = (const int*)d_in[3];

    float* outp = nullptr;
    float* attp = nullptr;
    long long os = (long long)out_size;
    if (os >= OUT_ELEMS + ATT_ELEMS) {
        outp = (float*)d_out;
        attp = (float*)d_out + OUT_ELEMS;
    } else if (os >= ATT_ELEMS) {
        attp = (float*)d_out;
    } else {
        outp = (float*)d_out;
    }

    cvt_all<<<QKV_BLOCKS + MBIT_BLOCKS, 256>>>(Q, K, V, M);

    cudaFuncSetAttribute(attn_kernel, cudaFuncAttributeMaxDynamicSharedMemorySize, SMEM_BYTES);
    dim3 grid(Ss / QT, BH);
    attn_kernel<<<grid, NTH, SMEM_BYTES>>>(outp, attp);
}